// round 14
// baseline (speedup 1.0000x reference)
#include <cuda_runtime.h>
#include <cuda_fp16.h>
#include <mma.h>

using namespace nvcuda;

#define NN 8192
#define DD 512
#define MAXDEG 512
#define NW 256   // bitmap words per row = 8192/32

// ---- scratch (device globals; no allocations allowed) ----
__device__ unsigned g_bitmap[NN * NW];     // 8 MB adjacency bitmap
__device__ int      g_cnt[NN];             // per-row nnz (excluding eye)
__device__ int      g_cols[NN * MAXDEG];   // per-row column lists (16 MB)
__device__ __half   g_xh[NN * DD];         // fp16 x
__device__ __half   g_wh[DD * DD];         // fp16 W (row-major)
__device__ __half   g_buf0h[NN * DD];      // h / diffusion ping (fp16)
__device__ __half   g_buf1h[NN * DD];      // diffusion pong (fp16)
__device__ float    g_outacc[NN * DD];     // weighted accumulation (fp32)

// ---------------------------------------------------------------------------
// 1) zero bitmap + counts
// ---------------------------------------------------------------------------
__global__ void zero_kernel() {
    int stride = gridDim.x * blockDim.x;
    int tid = blockIdx.x * blockDim.x + threadIdx.x;
    float4 z4 = make_float4(0.f, 0.f, 0.f, 0.f);
    float4* bm4 = (float4*)g_bitmap;
    for (int i = tid; i < NN * NW / 4; i += stride) bm4[i] = z4;
    for (int i = tid; i < NN; i += stride) g_cnt[i] = 0;
}

// ---------------------------------------------------------------------------
// 2) build dedup'd adjacency lists
// ---------------------------------------------------------------------------
__device__ __forceinline__ void adj_insert(int r, int c) {
    unsigned m = 1u << (c & 31);
    unsigned old = atomicOr(&g_bitmap[r * NW + (c >> 5)], m);
    if (!(old & m)) {
        int k = atomicAdd(&g_cnt[r], 1);
        if (k < MAXDEG) g_cols[r * MAXDEG + k] = c;
    }
}

__global__ __launch_bounds__(256) void build_kernel(const int* __restrict__ ei, int E) {
    int e = blockIdx.x * blockDim.x + threadIdx.x;
    if (e >= E) return;
    int r = ei[e];
    int c = ei[E + e];
    adj_insert(r, c);
    adj_insert(c, r);
}

// ---------------------------------------------------------------------------
// 2b) convert x and W to fp16
// ---------------------------------------------------------------------------
__global__ void cvt_kernel(const float* __restrict__ X, const float* __restrict__ Wm) {
    const int NX = NN * DD / 8;
    const int TOT = NX + DD * DD / 8;
    int stride = gridDim.x * blockDim.x;
    for (int i = blockIdx.x * blockDim.x + threadIdx.x; i < TOT; i += stride) {
        const float* src;
        __half* dst;
        int off;
        if (i < NX) { src = X; dst = g_xh; off = i * 8; }
        else        { src = Wm; dst = g_wh; off = (i - NX) * 8; }
        float4 f0 = *(const float4*)&src[off];
        float4 f1 = *(const float4*)&src[off + 4];
        __half2 h0 = __floats2half2_rn(f0.x, f0.y);
        __half2 h1 = __floats2half2_rn(f0.z, f0.w);
        __half2 h2 = __floats2half2_rn(f1.x, f1.y);
        __half2 h3 = __floats2half2_rn(f1.z, f1.w);
        uint4 hv;
        hv.x = *(unsigned*)&h0; hv.y = *(unsigned*)&h1;
        hv.z = *(unsigned*)&h2; hv.w = *(unsigned*)&h3;
        *(uint4*)&dst[off] = hv;
    }
}

// ---------------------------------------------------------------------------
// 3) HMMA GEMM + fused epilogue, 64x64 tiles for CTA parallelism
//    v = xh @ wh + b ; buf0h = fp16(v) ; outacc = dw0 * v
//    grid (8,128) = 1024 CTAs, 128 threads (4 warps 2x2), warp = 32x32
//    BK=32, register-prefetch double buffer (R8 structure)
// ---------------------------------------------------------------------------
#define ALD2 48   // A smem row stride (halves), 96B
#define BLD2 72   // B smem row stride (halves), 144B
#define CLD 20    // epilogue scratch ld (floats)

__global__ __launch_bounds__(128) void hgemm_kernel(const float* __restrict__ bvec,
                                                    const float* __restrict__ dw) {
    __shared__ union {
        struct {
            __half A[2][64 * ALD2];   // 64 rows x 32 k
            __half B[2][32 * BLD2];   // 32 k x 64 cols
        } mm;
        float c[4][16 * CLD];         // per-warp epilogue scratch
    } sm;

    int tid = threadIdx.x;
    int lane = tid & 31;
    int wid = tid >> 5;             // 0..3
    int wm = wid >> 1;              // 0..1 -> warp row (32 rows)
    int wn = wid & 1;               // 0..1 -> warp col (32 cols)
    int bm = blockIdx.y * 64;
    int bn = blockIdx.x * 64;

    // A loader: 64 rows x 32 halves; thread -> row ar, 2 x uint4 at ac, ac+8
    int ar = tid >> 1;              // 0..63
    int ac = (tid & 1) * 16;        // 0 or 16
    // B loader: 32 rows x 64 halves; thread -> row br, 2 x uint4 at bc, bc+8
    int br = tid >> 2;              // 0..31
    int bc = (tid & 3) * 16;        // 0,16,32,48

    wmma::fragment<wmma::accumulator, 16, 16, 16, float> fc[2][2];
#pragma unroll
    for (int i = 0; i < 2; ++i)
#pragma unroll
        for (int j = 0; j < 2; ++j) wmma::fill_fragment(fc[i][j], 0.0f);

    // prologue: tile 0 -> stage 0
    {
        *(uint4*)&sm.mm.A[0][ar * ALD2 + ac] = *(const uint4*)&g_xh[(size_t)(bm + ar) * DD + ac];
        *(uint4*)&sm.mm.A[0][ar * ALD2 + ac + 8] = *(const uint4*)&g_xh[(size_t)(bm + ar) * DD + ac + 8];
        *(uint4*)&sm.mm.B[0][br * BLD2 + bc] = *(const uint4*)&g_wh[(size_t)br * DD + bn + bc];
        *(uint4*)&sm.mm.B[0][br * BLD2 + bc + 8] = *(const uint4*)&g_wh[(size_t)br * DD + bn + bc + 8];
    }
    __syncthreads();

    int stage = 0;
    const int KT = DD / 32;   // 16
#pragma unroll 1
    for (int kt = 0; kt < KT; ++kt) {
        uint4 na0, na1, nb0, nb1;
        bool more = (kt + 1) < KT;
        if (more) {
            int k0 = (kt + 1) * 32;
            na0 = *(const uint4*)&g_xh[(size_t)(bm + ar) * DD + k0 + ac];
            na1 = *(const uint4*)&g_xh[(size_t)(bm + ar) * DD + k0 + ac + 8];
            nb0 = *(const uint4*)&g_wh[(size_t)(k0 + br) * DD + bn + bc];
            nb1 = *(const uint4*)&g_wh[(size_t)(k0 + br) * DD + bn + bc + 8];
        }
#pragma unroll
        for (int kk = 0; kk < 2; ++kk) {
            wmma::fragment<wmma::matrix_a, 16, 16, 16, __half, wmma::row_major> fa[2];
            wmma::fragment<wmma::matrix_b, 16, 16, 16, __half, wmma::row_major> fb[2];
#pragma unroll
            for (int i = 0; i < 2; ++i)
                wmma::load_matrix_sync(fa[i], &sm.mm.A[stage][(wm * 32 + i * 16) * ALD2 + kk * 16], ALD2);
#pragma unroll
            for (int j = 0; j < 2; ++j)
                wmma::load_matrix_sync(fb[j], &sm.mm.B[stage][(kk * 16) * BLD2 + wn * 32 + j * 16], BLD2);
#pragma unroll
            for (int i = 0; i < 2; ++i)
#pragma unroll
                for (int j = 0; j < 2; ++j)
                    wmma::mma_sync(fc[i][j], fa[i], fb[j], fc[i][j]);
        }
        if (more) {
            int ns = stage ^ 1;
            *(uint4*)&sm.mm.A[ns][ar * ALD2 + ac] = na0;
            *(uint4*)&sm.mm.A[ns][ar * ALD2 + ac + 8] = na1;
            *(uint4*)&sm.mm.B[ns][br * BLD2 + bc] = nb0;
            *(uint4*)&sm.mm.B[ns][br * BLD2 + bc + 8] = nb1;
            __syncthreads();
            stage = ns;
        }
    }

    // ---- fused epilogue: smem re-purposed as per-warp scratch ----
    __syncthreads();
    float w0 = dw[0];
    int er = lane >> 1;             // 0..15
    int ec = (lane & 1) * 8;        // 0 or 8
#pragma unroll
    for (int i = 0; i < 2; ++i)
#pragma unroll
        for (int j = 0; j < 2; ++j) {
            int row0 = bm + wm * 32 + i * 16;
            int col0 = bn + wn * 32 + j * 16;
            wmma::store_matrix_sync(&sm.c[wid][0], fc[i][j], CLD, wmma::mem_row_major);
            __syncwarp();
            float4 f0 = *(const float4*)&sm.c[wid][er * CLD + ec];
            float4 f1 = *(const float4*)&sm.c[wid][er * CLD + ec + 4];
            __syncwarp();
            float4 b0 = *(const float4*)&bvec[col0 + ec];
            float4 b1 = *(const float4*)&bvec[col0 + ec + 4];
            f0.x += b0.x; f0.y += b0.y; f0.z += b0.z; f0.w += b0.w;
            f1.x += b1.x; f1.y += b1.y; f1.z += b1.z; f1.w += b1.w;
            size_t base = (size_t)(row0 + er) * DD + col0 + ec;
            __half2 h0 = __floats2half2_rn(f0.x, f0.y);
            __half2 h1 = __floats2half2_rn(f0.z, f0.w);
            __half2 h2 = __floats2half2_rn(f1.x, f1.y);
            __half2 h3 = __floats2half2_rn(f1.z, f1.w);
            uint4 hv;
            hv.x = *(unsigned*)&h0; hv.y = *(unsigned*)&h1;
            hv.z = *(unsigned*)&h2; hv.w = *(unsigned*)&h3;
            *(uint4*)&g_buf0h[base] = hv;
            float4 o0, o1;
            o0.x = w0 * f0.x; o0.y = w0 * f0.y; o0.z = w0 * f0.z; o0.w = w0 * f0.w;
            o1.x = w0 * f1.x; o1.y = w0 * f1.y; o1.z = w0 * f1.z; o1.w = w0 * f1.w;
            *(float4*)&g_outacc[base] = o0;
            *(float4*)&g_outacc[base + 4] = o1;
        }
}

// ---------------------------------------------------------------------------
// 4) SpMM step (fp16 gather, pairwise HADD2 reduce, fp32 accumulate)
//    block = 128 threads = 2 rows; 64 lanes/row, each lane owns 8 halves
// ---------------------------------------------------------------------------
__device__ __forceinline__ void acc_add8(float* a, uint4 v) {
    float2 p0 = __half22float2(*(__half2*)&v.x);
    float2 p1 = __half22float2(*(__half2*)&v.y);
    float2 p2 = __half22float2(*(__half2*)&v.z);
    float2 p3 = __half22float2(*(__half2*)&v.w);
    a[0] += p0.x; a[1] += p0.y; a[2] += p1.x; a[3] += p1.y;
    a[4] += p2.x; a[5] += p2.y; a[6] += p3.x; a[7] += p3.y;
}

__device__ __forceinline__ uint4 hadd2_u4(uint4 a, uint4 b) {
    __half2* pa = (__half2*)&a;
    __half2* pb = (__half2*)&b;
    uint4 r;
    __half2* pr = (__half2*)&r;
    pr[0] = __hadd2(pa[0], pb[0]);
    pr[1] = __hadd2(pa[1], pb[1]);
    pr[2] = __hadd2(pa[2], pb[2]);
    pr[3] = __hadd2(pa[3], pb[3]);
    return r;
}

__global__ __launch_bounds__(128) void spmm_kernel(int src0, const float* __restrict__ dw,
                                                   int step, int last,
                                                   float* __restrict__ dout) {
    __shared__ int sc[2][MAXDEG];
    const __half* cur = src0 ? g_buf0h : g_buf1h;
    __half* nxt = src0 ? g_buf1h : g_buf0h;

    int tid = threadIdx.x;
    int hh = tid >> 6;
    int t = tid & 63;
    int row = blockIdx.x * 2 + hh;

    int n = g_cnt[row];
    if (n > MAXDEG) n = MAXDEG;
    for (int i = t; i < n; i += 64) sc[hh][i] = g_cols[row * MAXDEG + i];
    __syncthreads();

    const uint4* cv = (const uint4*)cur;
    float acc[8] = {};
    acc_add8(acc, cv[(size_t)row * 64 + t]);   // +eye self contribution

    const int* cols = sc[hh];
    int i = 0;
    for (; i + 8 <= n; i += 8) {
        uint4 v0 = cv[(size_t)cols[i + 0] * 64 + t];
        uint4 v1 = cv[(size_t)cols[i + 1] * 64 + t];
        uint4 v2 = cv[(size_t)cols[i + 2] * 64 + t];
        uint4 v3 = cv[(size_t)cols[i + 3] * 64 + t];
        uint4 v4 = cv[(size_t)cols[i + 4] * 64 + t];
        uint4 v5 = cv[(size_t)cols[i + 5] * 64 + t];
        uint4 v6 = cv[(size_t)cols[i + 6] * 64 + t];
        uint4 v7 = cv[(size_t)cols[i + 7] * 64 + t];
        // pairwise fp16 reduce (one fp16 add per element: negligible error)
        uint4 p0 = hadd2_u4(v0, v1);
        uint4 p1 = hadd2_u4(v2, v3);
        uint4 p2 = hadd2_u4(v4, v5);
        uint4 p3 = hadd2_u4(v6, v7);
        acc_add8(acc, p0); acc_add8(acc, p1);
        acc_add8(acc, p2); acc_add8(acc, p3);
    }
    for (; i < n; ++i) acc_add8(acc, cv[(size_t)cols[i] * 64 + t]);

    float s = 1.0f / (float)(n + 1);
    float w = dw[step];
    float r[8];
#pragma unroll
    for (int j = 0; j < 8; ++j) r[j] = acc[j] * s;

    size_t base = (size_t)row * DD + (size_t)t * 8;
    float4 o0 = *(const float4*)&g_outacc[base];
    float4 o1 = *(const float4*)&g_outacc[base + 4];
    if (!last) {
        __half2 h0 = __floats2half2_rn(r[0], r[1]);
        __half2 h1 = __floats2half2_rn(r[2], r[3]);
        __half2 h2 = __floats2half2_rn(r[4], r[5]);
        __half2 h3 = __floats2half2_rn(r[6], r[7]);
        uint4 hv;
        hv.x = *(unsigned*)&h0; hv.y = *(unsigned*)&h1;
        hv.z = *(unsigned*)&h2; hv.w = *(unsigned*)&h3;
        *(uint4*)&nxt[base] = hv;
        o0.x += w * r[0]; o0.y += w * r[1]; o0.z += w * r[2]; o0.w += w * r[3];
        o1.x += w * r[4]; o1.y += w * r[5]; o1.z += w * r[6]; o1.w += w * r[7];
        *(float4*)&g_outacc[base] = o0;
        *(float4*)&g_outacc[base + 4] = o1;
    } else {
        float4 q0, q1;
        q0.x = fmaxf(o0.x + w * r[0], 0.0f);
        q0.y = fmaxf(o0.y + w * r[1], 0.0f);
        q0.z = fmaxf(o0.z + w * r[2], 0.0f);
        q0.w = fmaxf(o0.w + w * r[3], 0.0f);
        q1.x = fmaxf(o1.x + w * r[4], 0.0f);
        q1.y = fmaxf(o1.y + w * r[5], 0.0f);
        q1.z = fmaxf(o1.z + w * r[6], 0.0f);
        q1.w = fmaxf(o1.w + w * r[7], 0.0f);
        *(float4*)&dout[base] = q0;
        *(float4*)&dout[base + 4] = q1;
    }
}

// ---------------------------------------------------------------------------
extern "C" void kernel_launch(void* const* d_in, const int* in_sizes, int n_in,
                              void* d_out, int out_size) {
    const float* x  = (const float*)d_in[0];
    const int*   ei = (const int*)d_in[1];
    const float* W  = (const float*)d_in[2];
    const float* b  = (const float*)d_in[3];
    const float* dw = (const float*)d_in[4];
    float* out = (float*)d_out;
    int E = in_sizes[1] / 2;

    zero_kernel<<<2048, 256>>>();
    build_kernel<<<(E + 255) / 256, 256>>>(ei, E);
    cvt_kernel<<<1024, 256>>>(x, W);
    hgemm_kernel<<<dim3(DD / 64, NN / 64), 128>>>(b, dw);
    spmm_kernel<<<NN / 2, 128>>>(1, dw, 1, 0, out);   // buf0h -> buf1h
    spmm_kernel<<<NN / 2, 128>>>(0, dw, 2, 0, out);   // buf1h -> buf0h
    spmm_kernel<<<NN / 2, 128>>>(1, dw, 3, 1, out);   // buf0h -> d_out (relu)
}

// round 16
// speedup vs baseline: 1.0929x; 1.0929x over previous
#include <cuda_runtime.h>
#include <cuda_fp16.h>
#include <mma.h>

using namespace nvcuda;

#define NN 8192
#define DD 512
#define MAXDEG 512
#define NW 256   // bitmap words per row = 8192/32

// ---- scratch (device globals; no allocations allowed) ----
__device__ unsigned g_bitmap[NN * NW];     // 8 MB adjacency bitmap
__device__ int      g_cnt[NN];             // per-row nnz (excluding eye)
__device__ int      g_cols[NN * MAXDEG];   // per-row column lists (16 MB)
__device__ __half   g_xh[NN * DD];         // fp16 x
__device__ __half   g_wh[DD * DD];         // fp16 W (row-major)
__device__ __half   g_buf0h[NN * DD];      // h / diffusion ping (fp16)
__device__ __half   g_buf1h[NN * DD];      // diffusion pong (fp16)
__device__ float    g_outacc[NN * DD];     // weighted accumulation (fp32)

// ---------------------------------------------------------------------------
// 1) zero bitmap + counts, fused with x/W fp16 conversion (independent loops)
// ---------------------------------------------------------------------------
__global__ void prep_kernel(const float* __restrict__ X, const float* __restrict__ Wm) {
    int stride = gridDim.x * blockDim.x;
    int tid = blockIdx.x * blockDim.x + threadIdx.x;
    // zero bitmap + counts
    float4 z4 = make_float4(0.f, 0.f, 0.f, 0.f);
    float4* bm4 = (float4*)g_bitmap;
    for (int i = tid; i < NN * NW / 4; i += stride) bm4[i] = z4;
    for (int i = tid; i < NN; i += stride) g_cnt[i] = 0;
    // convert x and W to fp16
    const int NX = NN * DD / 8;
    const int TOT = NX + DD * DD / 8;
    for (int i = tid; i < TOT; i += stride) {
        const float* src;
        __half* dst;
        int off;
        if (i < NX) { src = X; dst = g_xh; off = i * 8; }
        else        { src = Wm; dst = g_wh; off = (i - NX) * 8; }
        float4 f0 = *(const float4*)&src[off];
        float4 f1 = *(const float4*)&src[off + 4];
        __half2 h0 = __floats2half2_rn(f0.x, f0.y);
        __half2 h1 = __floats2half2_rn(f0.z, f0.w);
        __half2 h2 = __floats2half2_rn(f1.x, f1.y);
        __half2 h3 = __floats2half2_rn(f1.z, f1.w);
        uint4 hv;
        hv.x = *(unsigned*)&h0; hv.y = *(unsigned*)&h1;
        hv.z = *(unsigned*)&h2; hv.w = *(unsigned*)&h3;
        *(uint4*)&dst[off] = hv;
    }
}

// ---------------------------------------------------------------------------
// 2) build dedup'd adjacency lists
// ---------------------------------------------------------------------------
__device__ __forceinline__ void adj_insert(int r, int c) {
    unsigned m = 1u << (c & 31);
    unsigned old = atomicOr(&g_bitmap[r * NW + (c >> 5)], m);
    if (!(old & m)) {
        int k = atomicAdd(&g_cnt[r], 1);
        if (k < MAXDEG) g_cols[r * MAXDEG + k] = c;
    }
}

__global__ __launch_bounds__(256) void build_kernel(const int* __restrict__ ei, int E) {
    int e = blockIdx.x * blockDim.x + threadIdx.x;
    if (e >= E) return;
    int r = ei[e];
    int c = ei[E + e];
    adj_insert(r, c);
    adj_insert(c, r);
}

// ---------------------------------------------------------------------------
// 3) HMMA GEMM + fused epilogue (R8 config — measured best at 27.4us):
//    v = xh @ wh + b ; buf0h = fp16(v) ; outacc = dw0 * v
//    128x128 block tile, BK=32, 256 threads (8 warps, 4x2), warp = 32x64
//    register-prefetch double buffer, static smem union
// ---------------------------------------------------------------------------
#define HBK 32
#define ALD 48    // A smem ld (halves)
#define BLD 136   // B smem ld (halves)
#define CLD 20    // epilogue scratch ld (floats)

__global__ __launch_bounds__(256) void hgemm_kernel(const float* __restrict__ bvec,
                                                    const float* __restrict__ dw) {
    __shared__ union {
        struct {
            __half A[2][128 * ALD];
            __half B[2][HBK * BLD];
        } mm;
        float c[8][16 * CLD];   // per-warp epilogue scratch
    } sm;

    int tid = threadIdx.x;
    int lane = tid & 31;
    int wid = tid >> 5;
    int wm = wid >> 1;              // 0..3 -> warp row (32 rows each)
    int wn = wid & 1;               // 0..1 -> warp col (64 cols each)
    int bm = blockIdx.y * 128;
    int bn = blockIdx.x * 128;

    int ar = tid >> 2;              // 0..63
    int ac = (tid & 3) * 8;         // 0,8,16,24
    int br = tid >> 4;              // 0..15
    int bc = (tid & 15) * 8;        // 0..120

    wmma::fragment<wmma::accumulator, 16, 16, 16, float> fc[2][4];
#pragma unroll
    for (int i = 0; i < 2; ++i)
#pragma unroll
        for (int j = 0; j < 4; ++j) wmma::fill_fragment(fc[i][j], 0.0f);

    // prologue: tile 0
    {
        *(uint4*)&sm.mm.A[0][ar * ALD + ac] = *(const uint4*)&g_xh[(size_t)(bm + ar) * DD + ac];
        *(uint4*)&sm.mm.A[0][(ar + 64) * ALD + ac] = *(const uint4*)&g_xh[(size_t)(bm + ar + 64) * DD + ac];
        *(uint4*)&sm.mm.B[0][br * BLD + bc] = *(const uint4*)&g_wh[(size_t)br * DD + bn + bc];
        *(uint4*)&sm.mm.B[0][(br + 16) * BLD + bc] = *(const uint4*)&g_wh[(size_t)(br + 16) * DD + bn + bc];
    }
    __syncthreads();

    int stage = 0;
    const int KT = DD / HBK;   // 16
#pragma unroll 1
    for (int kt = 0; kt < KT; ++kt) {
        uint4 na0, na1, nb0, nb1;
        bool more = (kt + 1) < KT;
        if (more) {
            int k0 = (kt + 1) * HBK;
            na0 = *(const uint4*)&g_xh[(size_t)(bm + ar) * DD + k0 + ac];
            na1 = *(const uint4*)&g_xh[(size_t)(bm + ar + 64) * DD + k0 + ac];
            nb0 = *(const uint4*)&g_wh[(size_t)(k0 + br) * DD + bn + bc];
            nb1 = *(const uint4*)&g_wh[(size_t)(k0 + br + 16) * DD + bn + bc];
        }
#pragma unroll
        for (int kk = 0; kk < 2; ++kk) {
            wmma::fragment<wmma::matrix_a, 16, 16, 16, __half, wmma::row_major> fa[2];
            wmma::fragment<wmma::matrix_b, 16, 16, 16, __half, wmma::row_major> fb[4];
#pragma unroll
            for (int i = 0; i < 2; ++i)
                wmma::load_matrix_sync(fa[i], &sm.mm.A[stage][(wm * 32 + i * 16) * ALD + kk * 16], ALD);
#pragma unroll
            for (int j = 0; j < 4; ++j)
                wmma::load_matrix_sync(fb[j], &sm.mm.B[stage][(kk * 16) * BLD + wn * 64 + j * 16], BLD);
#pragma unroll
            for (int i = 0; i < 2; ++i)
#pragma unroll
                for (int j = 0; j < 4; ++j)
                    wmma::mma_sync(fc[i][j], fa[i], fb[j], fc[i][j]);
        }
        if (more) {
            int ns = stage ^ 1;
            *(uint4*)&sm.mm.A[ns][ar * ALD + ac] = na0;
            *(uint4*)&sm.mm.A[ns][(ar + 64) * ALD + ac] = na1;
            *(uint4*)&sm.mm.B[ns][br * BLD + bc] = nb0;
            *(uint4*)&sm.mm.B[ns][(br + 16) * BLD + bc] = nb1;
            __syncthreads();
            stage = ns;
        }
    }

    // ---- fused epilogue: smem re-purposed as per-warp scratch ----
    __syncthreads();
    float w0 = dw[0];
    int er = lane >> 1;             // 0..15
    int ec = (lane & 1) * 8;        // 0 or 8
#pragma unroll
    for (int i = 0; i < 2; ++i)
#pragma unroll
        for (int j = 0; j < 4; ++j) {
            int row0 = bm + wm * 32 + i * 16;
            int col0 = bn + wn * 64 + j * 16;
            wmma::store_matrix_sync(&sm.c[wid][0], fc[i][j], CLD, wmma::mem_row_major);
            __syncwarp();
            float4 f0 = *(const float4*)&sm.c[wid][er * CLD + ec];
            float4 f1 = *(const float4*)&sm.c[wid][er * CLD + ec + 4];
            __syncwarp();
            float4 b0 = *(const float4*)&bvec[col0 + ec];
            float4 b1 = *(const float4*)&bvec[col0 + ec + 4];
            f0.x += b0.x; f0.y += b0.y; f0.z += b0.z; f0.w += b0.w;
            f1.x += b1.x; f1.y += b1.y; f1.z += b1.z; f1.w += b1.w;
            size_t base = (size_t)(row0 + er) * DD + col0 + ec;
            __half2 h0 = __floats2half2_rn(f0.x, f0.y);
            __half2 h1 = __floats2half2_rn(f0.z, f0.w);
            __half2 h2 = __floats2half2_rn(f1.x, f1.y);
            __half2 h3 = __floats2half2_rn(f1.z, f1.w);
            uint4 hv;
            hv.x = *(unsigned*)&h0; hv.y = *(unsigned*)&h1;
            hv.z = *(unsigned*)&h2; hv.w = *(unsigned*)&h3;
            *(uint4*)&g_buf0h[base] = hv;
            float4 o0, o1;
            o0.x = w0 * f0.x; o0.y = w0 * f0.y; o0.z = w0 * f0.z; o0.w = w0 * f0.w;
            o1.x = w0 * f1.x; o1.y = w0 * f1.y; o1.z = w0 * f1.z; o1.w = w0 * f1.w;
            *(float4*)&g_outacc[base] = o0;
            *(float4*)&g_outacc[base + 4] = o1;
        }
}

// ---------------------------------------------------------------------------
// 4) SpMM step (fp16 gather, pairwise HADD2 reduce, fp32 accumulate)
//    block = 128 threads = 2 rows; 64 lanes/row, each lane owns 8 halves
// ---------------------------------------------------------------------------
__device__ __forceinline__ void acc_add8(float* a, uint4 v) {
    float2 p0 = __half22float2(*(__half2*)&v.x);
    float2 p1 = __half22float2(*(__half2*)&v.y);
    float2 p2 = __half22float2(*(__half2*)&v.z);
    float2 p3 = __half22float2(*(__half2*)&v.w);
    a[0] += p0.x; a[1] += p0.y; a[2] += p1.x; a[3] += p1.y;
    a[4] += p2.x; a[5] += p2.y; a[6] += p3.x; a[7] += p3.y;
}

__device__ __forceinline__ uint4 hadd2_u4(uint4 a, uint4 b) {
    __half2* pa = (__half2*)&a;
    __half2* pb = (__half2*)&b;
    uint4 r;
    __half2* pr = (__half2*)&r;
    pr[0] = __hadd2(pa[0], pb[0]);
    pr[1] = __hadd2(pa[1], pb[1]);
    pr[2] = __hadd2(pa[2], pb[2]);
    pr[3] = __hadd2(pa[3], pb[3]);
    return r;
}

__global__ __launch_bounds__(128) void spmm_kernel(int src0, const float* __restrict__ dw,
                                                   int step, int last,
                                                   float* __restrict__ dout) {
    __shared__ int sc[2][MAXDEG];
    const __half* cur = src0 ? g_buf0h : g_buf1h;
    __half* nxt = src0 ? g_buf1h : g_buf0h;

    int tid = threadIdx.x;
    int hh = tid >> 6;
    int t = tid & 63;
    int row = blockIdx.x * 2 + hh;

    int n = g_cnt[row];
    if (n > MAXDEG) n = MAXDEG;
    for (int i = t; i < n; i += 64) sc[hh][i] = g_cols[row * MAXDEG + i];
    __syncthreads();

    const uint4* cv = (const uint4*)cur;
    float acc[8] = {};
    acc_add8(acc, cv[(size_t)row * 64 + t]);   // +eye self contribution

    const int* cols = sc[hh];
    int i = 0;
    for (; i + 8 <= n; i += 8) {
        uint4 v0 = cv[(size_t)cols[i + 0] * 64 + t];
        uint4 v1 = cv[(size_t)cols[i + 1] * 64 + t];
        uint4 v2 = cv[(size_t)cols[i + 2] * 64 + t];
        uint4 v3 = cv[(size_t)cols[i + 3] * 64 + t];
        uint4 v4 = cv[(size_t)cols[i + 4] * 64 + t];
        uint4 v5 = cv[(size_t)cols[i + 5] * 64 + t];
        uint4 v6 = cv[(size_t)cols[i + 6] * 64 + t];
        uint4 v7 = cv[(size_t)cols[i + 7] * 64 + t];
        // pairwise fp16 reduce (one fp16 add per element: negligible error)
        uint4 p0 = hadd2_u4(v0, v1);
        uint4 p1 = hadd2_u4(v2, v3);
        uint4 p2 = hadd2_u4(v4, v5);
        uint4 p3 = hadd2_u4(v6, v7);
        acc_add8(acc, p0); acc_add8(acc, p1);
        acc_add8(acc, p2); acc_add8(acc, p3);
    }
    for (; i < n; ++i) acc_add8(acc, cv[(size_t)cols[i] * 64 + t]);

    float s = 1.0f / (float)(n + 1);
    float w = dw[step];
    float r[8];
#pragma unroll
    for (int j = 0; j < 8; ++j) r[j] = acc[j] * s;

    size_t base = (size_t)row * DD + (size_t)t * 8;
    float4 o0 = *(const float4*)&g_outacc[base];
    float4 o1 = *(const float4*)&g_outacc[base + 4];
    if (!last) {
        __half2 h0 = __floats2half2_rn(r[0], r[1]);
        __half2 h1 = __floats2half2_rn(r[2], r[3]);
        __half2 h2 = __floats2half2_rn(r[4], r[5]);
        __half2 h3 = __floats2half2_rn(r[6], r[7]);
        uint4 hv;
        hv.x = *(unsigned*)&h0; hv.y = *(unsigned*)&h1;
        hv.z = *(unsigned*)&h2; hv.w = *(unsigned*)&h3;
        *(uint4*)&nxt[base] = hv;
        o0.x += w * r[0]; o0.y += w * r[1]; o0.z += w * r[2]; o0.w += w * r[3];
        o1.x += w * r[4]; o1.y += w * r[5]; o1.z += w * r[6]; o1.w += w * r[7];
        *(float4*)&g_outacc[base] = o0;
        *(float4*)&g_outacc[base + 4] = o1;
    } else {
        float4 q0, q1;
        q0.x = fmaxf(o0.x + w * r[0], 0.0f);
        q0.y = fmaxf(o0.y + w * r[1], 0.0f);
        q0.z = fmaxf(o0.z + w * r[2], 0.0f);
        q0.w = fmaxf(o0.w + w * r[3], 0.0f);
        q1.x = fmaxf(o1.x + w * r[4], 0.0f);
        q1.y = fmaxf(o1.y + w * r[5], 0.0f);
        q1.z = fmaxf(o1.z + w * r[6], 0.0f);
        q1.w = fmaxf(o1.w + w * r[7], 0.0f);
        *(float4*)&dout[base] = q0;
        *(float4*)&dout[base + 4] = q1;
    }
}

// ---------------------------------------------------------------------------
extern "C" void kernel_launch(void* const* d_in, const int* in_sizes, int n_in,
                              void* d_out, int out_size) {
    const float* x  = (const float*)d_in[0];
    const int*   ei = (const int*)d_in[1];
    const float* W  = (const float*)d_in[2];
    const float* b  = (const float*)d_in[3];
    const float* dw = (const float*)d_in[4];
    float* out = (float*)d_out;
    int E = in_sizes[1] / 2;

    prep_kernel<<<2048, 256>>>(x, W);
    build_kernel<<<(E + 255) / 256, 256>>>(ei, E);
    hgemm_kernel<<<dim3(DD / 128, NN / 128), 256>>>(b, dw);
    spmm_kernel<<<NN / 2, 128>>>(1, dw, 1, 0, out);   // buf0h -> buf1h
    spmm_kernel<<<NN / 2, 128>>>(0, dw, 2, 0, out);   // buf1h -> buf0h
    spmm_kernel<<<NN / 2, 128>>>(1, dw, 3, 1, out);   // buf0h -> d_out (relu)
}

// round 17
// speedup vs baseline: 1.1074x; 1.0132x over previous
#include <cuda_runtime.h>
#include <cuda_fp16.h>
#include <mma.h>

using namespace nvcuda;

#define NN 8192
#define DD 512
#define MAXDEG 512
#define NW 256   // bitmap words per row = 8192/32

// ---- scratch (device globals; no allocations allowed) ----
__device__ unsigned g_bitmap[NN * NW];     // 8 MB adjacency bitmap
__device__ int      g_cnt[NN];             // per-row nnz (excluding eye)
__device__ int      g_cols[NN * MAXDEG];   // per-row column lists (16 MB)
__device__ __half   g_xh[NN * DD];         // fp16 x
__device__ __half   g_wh[DD * DD];         // fp16 W (row-major)
__device__ __half   g_buf0h[NN * DD];      // h / diffusion ping (fp16)
__device__ __half   g_buf1h[NN * DD];      // diffusion pong (fp16)
__device__ float    g_outacc[NN * DD];     // weighted accumulation (fp32)

// ---------------------------------------------------------------------------
// 1) zero bitmap + counts, fused with x/W fp16 conversion (independent loops)
// ---------------------------------------------------------------------------
__global__ void prep_kernel(const float* __restrict__ X, const float* __restrict__ Wm) {
    int stride = gridDim.x * blockDim.x;
    int tid = blockIdx.x * blockDim.x + threadIdx.x;
    // zero bitmap + counts
    float4 z4 = make_float4(0.f, 0.f, 0.f, 0.f);
    float4* bm4 = (float4*)g_bitmap;
    for (int i = tid; i < NN * NW / 4; i += stride) bm4[i] = z4;
    for (int i = tid; i < NN; i += stride) g_cnt[i] = 0;
    // convert x and W to fp16
    const int NX = NN * DD / 8;
    const int TOT = NX + DD * DD / 8;
    for (int i = tid; i < TOT; i += stride) {
        const float* src;
        __half* dst;
        int off;
        if (i < NX) { src = X; dst = g_xh; off = i * 8; }
        else        { src = Wm; dst = g_wh; off = (i - NX) * 8; }
        float4 f0 = *(const float4*)&src[off];
        float4 f1 = *(const float4*)&src[off + 4];
        __half2 h0 = __floats2half2_rn(f0.x, f0.y);
        __half2 h1 = __floats2half2_rn(f0.z, f0.w);
        __half2 h2 = __floats2half2_rn(f1.x, f1.y);
        __half2 h3 = __floats2half2_rn(f1.z, f1.w);
        uint4 hv;
        hv.x = *(unsigned*)&h0; hv.y = *(unsigned*)&h1;
        hv.z = *(unsigned*)&h2; hv.w = *(unsigned*)&h3;
        *(uint4*)&dst[off] = hv;
    }
}

// ---------------------------------------------------------------------------
// 2) build dedup'd adjacency lists
// ---------------------------------------------------------------------------
__device__ __forceinline__ void adj_insert(int r, int c) {
    unsigned m = 1u << (c & 31);
    unsigned old = atomicOr(&g_bitmap[r * NW + (c >> 5)], m);
    if (!(old & m)) {
        int k = atomicAdd(&g_cnt[r], 1);
        if (k < MAXDEG) g_cols[r * MAXDEG + k] = c;
    }
}

__global__ __launch_bounds__(256) void build_kernel(const int* __restrict__ ei, int E) {
    int e = blockIdx.x * blockDim.x + threadIdx.x;
    if (e >= E) return;
    int r = ei[e];
    int c = ei[E + e];
    adj_insert(r, c);
    adj_insert(c, r);
}

// ---------------------------------------------------------------------------
// 3) HMMA GEMM + fused epilogue (R8 config, ALD 48->40 to halve A-fragment
//    ldmatrix bank conflicts):
//    v = xh @ wh + b ; buf0h = fp16(v) ; outacc = dw0 * v
//    128x128 block tile, BK=32, 256 threads (8 warps, 4x2), warp = 32x64
// ---------------------------------------------------------------------------
#define HBK 32
#define ALD 40    // A smem ld (halves), 80B rows: 20 words -> 2-way conflicts
#define BLD 136   // B smem ld (halves), 272B rows
#define CLD 20    // epilogue scratch ld (floats)

__global__ __launch_bounds__(256) void hgemm_kernel(const float* __restrict__ bvec,
                                                    const float* __restrict__ dw) {
    __shared__ union {
        struct {
            __half A[2][128 * ALD];
            __half B[2][HBK * BLD];
        } mm;
        float c[8][16 * CLD];   // per-warp epilogue scratch
    } sm;

    int tid = threadIdx.x;
    int lane = tid & 31;
    int wid = tid >> 5;
    int wm = wid >> 1;              // 0..3 -> warp row (32 rows each)
    int wn = wid & 1;               // 0..1 -> warp col (64 cols each)
    int bm = blockIdx.y * 128;
    int bn = blockIdx.x * 128;

    int ar = tid >> 2;              // 0..63
    int ac = (tid & 3) * 8;         // 0,8,16,24
    int br = tid >> 4;              // 0..15
    int bc = (tid & 15) * 8;        // 0..120

    wmma::fragment<wmma::accumulator, 16, 16, 16, float> fc[2][4];
#pragma unroll
    for (int i = 0; i < 2; ++i)
#pragma unroll
        for (int j = 0; j < 4; ++j) wmma::fill_fragment(fc[i][j], 0.0f);

    // prologue: tile 0
    {
        *(uint4*)&sm.mm.A[0][ar * ALD + ac] = *(const uint4*)&g_xh[(size_t)(bm + ar) * DD + ac];
        *(uint4*)&sm.mm.A[0][(ar + 64) * ALD + ac] = *(const uint4*)&g_xh[(size_t)(bm + ar + 64) * DD + ac];
        *(uint4*)&sm.mm.B[0][br * BLD + bc] = *(const uint4*)&g_wh[(size_t)br * DD + bn + bc];
        *(uint4*)&sm.mm.B[0][(br + 16) * BLD + bc] = *(const uint4*)&g_wh[(size_t)(br + 16) * DD + bn + bc];
    }
    __syncthreads();

    int stage = 0;
    const int KT = DD / HBK;   // 16
#pragma unroll 1
    for (int kt = 0; kt < KT; ++kt) {
        uint4 na0, na1, nb0, nb1;
        bool more = (kt + 1) < KT;
        if (more) {
            int k0 = (kt + 1) * HBK;
            na0 = *(const uint4*)&g_xh[(size_t)(bm + ar) * DD + k0 + ac];
            na1 = *(const uint4*)&g_xh[(size_t)(bm + ar + 64) * DD + k0 + ac];
            nb0 = *(const uint4*)&g_wh[(size_t)(k0 + br) * DD + bn + bc];
            nb1 = *(const uint4*)&g_wh[(size_t)(k0 + br + 16) * DD + bn + bc];
        }
#pragma unroll
        for (int kk = 0; kk < 2; ++kk) {
            wmma::fragment<wmma::matrix_a, 16, 16, 16, __half, wmma::row_major> fa[2];
            wmma::fragment<wmma::matrix_b, 16, 16, 16, __half, wmma::row_major> fb[4];
#pragma unroll
            for (int i = 0; i < 2; ++i)
                wmma::load_matrix_sync(fa[i], &sm.mm.A[stage][(wm * 32 + i * 16) * ALD + kk * 16], ALD);
#pragma unroll
            for (int j = 0; j < 4; ++j)
                wmma::load_matrix_sync(fb[j], &sm.mm.B[stage][(kk * 16) * BLD + wn * 64 + j * 16], BLD);
#pragma unroll
            for (int i = 0; i < 2; ++i)
#pragma unroll
                for (int j = 0; j < 4; ++j)
                    wmma::mma_sync(fc[i][j], fa[i], fb[j], fc[i][j]);
        }
        if (more) {
            int ns = stage ^ 1;
            *(uint4*)&sm.mm.A[ns][ar * ALD + ac] = na0;
            *(uint4*)&sm.mm.A[ns][(ar + 64) * ALD + ac] = na1;
            *(uint4*)&sm.mm.B[ns][br * BLD + bc] = nb0;
            *(uint4*)&sm.mm.B[ns][(br + 16) * BLD + bc] = nb1;
            __syncthreads();
            stage = ns;
        }
    }

    // ---- fused epilogue: smem re-purposed as per-warp scratch ----
    __syncthreads();
    float w0 = dw[0];
    int er = lane >> 1;             // 0..15
    int ec = (lane & 1) * 8;        // 0 or 8
#pragma unroll
    for (int i = 0; i < 2; ++i)
#pragma unroll
        for (int j = 0; j < 4; ++j) {
            int row0 = bm + wm * 32 + i * 16;
            int col0 = bn + wn * 64 + j * 16;
            wmma::store_matrix_sync(&sm.c[wid][0], fc[i][j], CLD, wmma::mem_row_major);
            __syncwarp();
            float4 f0 = *(const float4*)&sm.c[wid][er * CLD + ec];
            float4 f1 = *(const float4*)&sm.c[wid][er * CLD + ec + 4];
            __syncwarp();
            float4 b0 = *(const float4*)&bvec[col0 + ec];
            float4 b1 = *(const float4*)&bvec[col0 + ec + 4];
            f0.x += b0.x; f0.y += b0.y; f0.z += b0.z; f0.w += b0.w;
            f1.x += b1.x; f1.y += b1.y; f1.z += b1.z; f1.w += b1.w;
            size_t base = (size_t)(row0 + er) * DD + col0 + ec;
            __half2 h0 = __floats2half2_rn(f0.x, f0.y);
            __half2 h1 = __floats2half2_rn(f0.z, f0.w);
            __half2 h2 = __floats2half2_rn(f1.x, f1.y);
            __half2 h3 = __floats2half2_rn(f1.z, f1.w);
            uint4 hv;
            hv.x = *(unsigned*)&h0; hv.y = *(unsigned*)&h1;
            hv.z = *(unsigned*)&h2; hv.w = *(unsigned*)&h3;
            *(uint4*)&g_buf0h[base] = hv;
            float4 o0, o1;
            o0.x = w0 * f0.x; o0.y = w0 * f0.y; o0.z = w0 * f0.z; o0.w = w0 * f0.w;
            o1.x = w0 * f1.x; o1.y = w0 * f1.y; o1.z = w0 * f1.z; o1.w = w0 * f1.w;
            *(float4*)&g_outacc[base] = o0;
            *(float4*)&g_outacc[base + 4] = o1;
        }
}

// ---------------------------------------------------------------------------
// 4) SpMM step (fp16 gather, pairwise HADD2 reduce, fp32 accumulate)
//    block = 128 threads = 2 rows; 64 lanes/row, each lane owns 8 halves
// ---------------------------------------------------------------------------
__device__ __forceinline__ void acc_add8(float* a, uint4 v) {
    float2 p0 = __half22float2(*(__half2*)&v.x);
    float2 p1 = __half22float2(*(__half2*)&v.y);
    float2 p2 = __half22float2(*(__half2*)&v.z);
    float2 p3 = __half22float2(*(__half2*)&v.w);
    a[0] += p0.x; a[1] += p0.y; a[2] += p1.x; a[3] += p1.y;
    a[4] += p2.x; a[5] += p2.y; a[6] += p3.x; a[7] += p3.y;
}

__device__ __forceinline__ uint4 hadd2_u4(uint4 a, uint4 b) {
    __half2* pa = (__half2*)&a;
    __half2* pb = (__half2*)&b;
    uint4 r;
    __half2* pr = (__half2*)&r;
    pr[0] = __hadd2(pa[0], pb[0]);
    pr[1] = __hadd2(pa[1], pb[1]);
    pr[2] = __hadd2(pa[2], pb[2]);
    pr[3] = __hadd2(pa[3], pb[3]);
    return r;
}

__global__ __launch_bounds__(128) void spmm_kernel(int src0, const float* __restrict__ dw,
                                                   int step, int last,
                                                   float* __restrict__ dout) {
    __shared__ int sc[2][MAXDEG];
    const __half* cur = src0 ? g_buf0h : g_buf1h;
    __half* nxt = src0 ? g_buf1h : g_buf0h;

    int tid = threadIdx.x;
    int hh = tid >> 6;
    int t = tid & 63;
    int row = blockIdx.x * 2 + hh;

    int n = g_cnt[row];
    if (n > MAXDEG) n = MAXDEG;
    for (int i = t; i < n; i += 64) sc[hh][i] = g_cols[row * MAXDEG + i];
    __syncthreads();

    const uint4* cv = (const uint4*)cur;
    float acc[8] = {};
    acc_add8(acc, cv[(size_t)row * 64 + t]);   // +eye self contribution

    const int* cols = sc[hh];
    int i = 0;
    for (; i + 8 <= n; i += 8) {
        uint4 v0 = cv[(size_t)cols[i + 0] * 64 + t];
        uint4 v1 = cv[(size_t)cols[i + 1] * 64 + t];
        uint4 v2 = cv[(size_t)cols[i + 2] * 64 + t];
        uint4 v3 = cv[(size_t)cols[i + 3] * 64 + t];
        uint4 v4 = cv[(size_t)cols[i + 4] * 64 + t];
        uint4 v5 = cv[(size_t)cols[i + 5] * 64 + t];
        uint4 v6 = cv[(size_t)cols[i + 6] * 64 + t];
        uint4 v7 = cv[(size_t)cols[i + 7] * 64 + t];
        // pairwise fp16 reduce (one fp16 add per element: negligible error)
        uint4 p0 = hadd2_u4(v0, v1);
        uint4 p1 = hadd2_u4(v2, v3);
        uint4 p2 = hadd2_u4(v4, v5);
        uint4 p3 = hadd2_u4(v6, v7);
        acc_add8(acc, p0); acc_add8(acc, p1);
        acc_add8(acc, p2); acc_add8(acc, p3);
    }
    for (; i < n; ++i) acc_add8(acc, cv[(size_t)cols[i] * 64 + t]);

    float s = 1.0f / (float)(n + 1);
    float w = dw[step];
    float r[8];
#pragma unroll
    for (int j = 0; j < 8; ++j) r[j] = acc[j] * s;

    size_t base = (size_t)row * DD + (size_t)t * 8;
    float4 o0 = *(const float4*)&g_outacc[base];
    float4 o1 = *(const float4*)&g_outacc[base + 4];
    if (!last) {
        __half2 h0 = __floats2half2_rn(r[0], r[1]);
        __half2 h1 = __floats2half2_rn(r[2], r[3]);
        __half2 h2 = __floats2half2_rn(r[4], r[5]);
        __half2 h3 = __floats2half2_rn(r[6], r[7]);
        uint4 hv;
        hv.x = *(unsigned*)&h0; hv.y = *(unsigned*)&h1;
        hv.z = *(unsigned*)&h2; hv.w = *(unsigned*)&h3;
        *(uint4*)&nxt[base] = hv;
        o0.x += w * r[0]; o0.y += w * r[1]; o0.z += w * r[2]; o0.w += w * r[3];
        o1.x += w * r[4]; o1.y += w * r[5]; o1.z += w * r[6]; o1.w += w * r[7];
        *(float4*)&g_outacc[base] = o0;
        *(float4*)&g_outacc[base + 4] = o1;
    } else {
        float4 q0, q1;
        q0.x = fmaxf(o0.x + w * r[0], 0.0f);
        q0.y = fmaxf(o0.y + w * r[1], 0.0f);
        q0.z = fmaxf(o0.z + w * r[2], 0.0f);
        q0.w = fmaxf(o0.w + w * r[3], 0.0f);
        q1.x = fmaxf(o1.x + w * r[4], 0.0f);
        q1.y = fmaxf(o1.y + w * r[5], 0.0f);
        q1.z = fmaxf(o1.z + w * r[6], 0.0f);
        q1.w = fmaxf(o1.w + w * r[7], 0.0f);
        *(float4*)&dout[base] = q0;
        *(float4*)&dout[base + 4] = q1;
    }
}

// ---------------------------------------------------------------------------
extern "C" void kernel_launch(void* const* d_in, const int* in_sizes, int n_in,
                              void* d_out, int out_size) {
    const float* x  = (const float*)d_in[0];
    const int*   ei = (const int*)d_in[1];
    const float* W  = (const float*)d_in[2];
    const float* b  = (const float*)d_in[3];
    const float* dw = (const float*)d_in[4];
    float* out = (float*)d_out;
    int E = in_sizes[1] / 2;

    prep_kernel<<<2048, 256>>>(x, W);
    build_kernel<<<(E + 255) / 256, 256>>>(ei, E);
    hgemm_kernel<<<dim3(DD / 128, NN / 128), 256>>>(b, dw);
    spmm_kernel<<<NN / 2, 128>>>(1, dw, 1, 0, out);   // buf0h -> buf1h
    spmm_kernel<<<NN / 2, 128>>>(0, dw, 2, 0, out);   // buf1h -> buf0h
    spmm_kernel<<<NN / 2, 128>>>(1, dw, 3, 1, out);   // buf0h -> d_out (relu)
}